// round 7
// baseline (speedup 1.0000x reference)
#include <cuda_runtime.h>

#define WW 512
#define HH 512
#define DD 64
#define NN 2
#define HS 8
#define SQRT2F 1.41421356237309515f
#define NBLK ((HH / HS) * (DD / 2) * NN)   /* 64*32*2 = 4096 */

// single-kernel finish scratch (graph-safe; last block resets for next replay)
__device__ float    g_acc = 0.0f;
__device__ unsigned g_cnt = 0;

// One fused step: emits the 48 stencil terms for output rows (d,h) and (d+1,h).
// All row offsets (jrow/jc2) and h-weights (wh1/wh2) are compile-time constants
// at every call site; shared differences: z0=v1, s0=u1, s1=u2.
__device__ __forceinline__ void step(
    const float* __restrict__ r0, const float* __restrict__ r1,
    const float* __restrict__ r2, const float* __restrict__ r3,
    int jrow, int jc2, int w0, int hw2, int hw1, bool lastw,
    float wh1, float wh2, float wzz0, float wzz1,
    float4& A0, float4& B0, float4& A1, float4& B1, float4& A2, float4& B2,
    float& a4, float& a5, float& b4, float& b5,
    float& c4, float& c5, float& d4, float& d5, float& e4, float& f4,
    float* u0, float* u1, float* u2,
    float& acc0, float& acc1, float& acc2, float& acc3)
{
    // fresh loads: rows h+2 of slabs d, d+1, d+2 (+halos) and row h of slab d+3
    const float4 C0 = *(const float4*)(r0 + jc2 * WW + w0);
    const float2 g0 = *(const float2*)(r0 + jc2 * WW + hw2);
    const float4 C1 = *(const float4*)(r1 + jc2 * WW + w0);
    const float2 g1 = *(const float2*)(r1 + jc2 * WW + hw2);
    const float4 C2 = *(const float4*)(r2 + jc2 * WW + w0);
    const float  g2 = (r2 + jc2 * WW)[hw1];
    const float4 Q3 = *(const float4*)(r3 + jrow * WW + w0);

    // x-differences of rows A0/A1 (tid127: clamp so edge terms cancel to 0)
    float dx0[5], dx1[5];
    dx0[0] = A0.x - A0.y; dx0[1] = A0.y - A0.z; dx0[2] = A0.z - A0.w;
    dx0[3] = lastw ? dx0[2] : (A0.w - a4);
    dx0[4] = lastw ? dx0[2] : (a4 - a5);
    dx1[0] = A1.x - A1.y; dx1[1] = A1.y - A1.z; dx1[2] = A1.z - A1.w;
    dx1[3] = lastw ? dx1[2] : (A1.w - c4);
    dx1[4] = lastw ? dx1[2] : (c4 - c5);

    float un0[4] = {B0.x - C0.x, B0.y - C0.y, B0.z - C0.z, B0.w - C0.w};
    float un1[4] = {B1.x - C1.x, B1.y - C1.y, B1.z - C1.z, B1.w - C1.w};
    float un2[4] = {B2.x - C2.x, B2.y - C2.y, B2.z - C2.z, B2.w - C2.w};

    const float u0_4 = lastw ? u0[3] : (a4 - b4);
    const float u1_4 = lastw ? u1[3] : (c4 - d4);

    // v (slab diffs at row h); z0 == v1
    float v0[5], v1[5];
    v0[0] = A0.x - A1.x; v0[1] = A0.y - A1.y; v0[2] = A0.z - A1.z; v0[3] = A0.w - A1.w;
    v0[4] = lastw ? v0[3] : (a4 - c4);
    v1[0] = A1.x - A2.x; v1[1] = A1.y - A2.y; v1[2] = A1.z - A2.z; v1[3] = A1.w - A2.w;
    v1[4] = lastw ? v1[3] : (c4 - e4);

    float z1[4] = {A2.x - Q3.x, A2.y - Q3.y, A2.z - Q3.z, A2.w - Q3.w};

    #pragma unroll
    for (int i = 0; i < 4; ++i) {
        const float u0n = (i < 3) ? u0[i + 1] : u0_4;
        const float u1n = (i < 3) ? u1[i + 1] : u1_4;
        // e = d
        acc0 += fabsf(dx0[i] - dx0[i + 1]);                      // g_xx
        acc1  = fmaf(wh2,          fabsf(u0[i] - un0[i]), acc1); // g_yy
        acc2  = fmaf(wzz0,         fabsf(v0[i] - v1[i]),  acc2); // g_zz (z0 = v1)
        acc3  = fmaf(2.0f * wh1,   fabsf(u0[i] - u0n),    acc3); // g_xy
        acc2  = fmaf(SQRT2F,       fabsf(v0[i] - v0[i+1]),acc2); // g_xz
        acc1  = fmaf(SQRT2F * wh1, fabsf(u0[i] - u1[i]),  acc1); // g_yz (s0 = u1)
        // e = d+1
        acc0 += fabsf(dx1[i] - dx1[i + 1]);
        acc1  = fmaf(wh2,          fabsf(u1[i] - un1[i]), acc1);
        acc2  = fmaf(wzz1,         fabsf(v1[i] - z1[i]),  acc2);
        acc3  = fmaf(2.0f * wh1,   fabsf(u1[i] - u1n),    acc3);
        acc2  = fmaf(SQRT2F,       fabsf(v1[i] - v1[i+1]),acc2);
        acc1  = fmaf(SQRT2F * wh1, fabsf(u1[i] - u2[i]),  acc1); // g_yz (s1 = u2)
    }

    // roll state (register renames under full unroll)
    A0 = B0; B0 = C0; A1 = B1; B1 = C1; A2 = B2; B2 = C2;
    a4 = b4; a5 = b5; b4 = g0.x; b5 = g0.y;
    c4 = d4; c5 = d5; d4 = g1.x; d5 = g1.y;
    e4 = f4; f4 = g2;
    u0[0] = un0[0]; u0[1] = un0[1]; u0[2] = un0[2]; u0[3] = un0[3];
    u1[0] = un1[0]; u1[1] = un1[1]; u1[2] = un1[2]; u1[3] = un1[3];
    u2[0] = un2[0]; u2[1] = un2[1]; u2[2] = un2[2]; u2[3] = un2[3];
}

__global__ __launch_bounds__(128, 6)
void hess_kernel(const float* __restrict__ x, float* __restrict__ out) {
    const int tid  = threadIdx.x;
    const int lane = tid & 31;
    const int w0   = tid << 2;                 // 128 * 4 = 512 = WW
    const int h0   = blockIdx.x * HS;
    const int d    = blockIdx.y * 2;           // output slabs d, d+1
    const int n    = blockIdx.z;
    const bool lastw = (tid == 127);

    const size_t slab = (size_t)HH * WW;
    const float* q0 = x + (size_t)(n * DD + d) * slab;      // slab d
    const float* q1 = q0 + slab;                            // slab d+1 (d<=62 -> valid)
    const float* q2 = (d + 2 < DD) ? q1 + slab : q1;        // clamp: v1 -> 0 self-cancel
    const float* q3 = (d + 3 < DD) ? q2 + slab : q2;
    const float wzz0 = (d + 2 < DD) ? 0.5f : 0.0f;          // masks g_zz at d-edges
    const float wzz1 = (d + 3 < DD) ? 0.5f : 0.0f;

    const int hw2 = lastw ? (WW - 2) : (w0 + 4);            // float2 halo (clamped tid127)
    const int hw1 = lastw ? (WW - 1) : (w0 + 4);            // scalar halo

    const float* r0 = q0 + h0 * WW;
    const float* r1 = q1 + h0 * WW;
    const float* r2 = q2 + h0 * WW;
    const float* r3 = q3 + h0 * WW;

    // prologue: rows h0, h0+1 of slabs d, d+1, d+2 (+halos)
    float4 A0 = *(const float4*)(r0 + w0);
    float4 B0 = *(const float4*)(r0 + WW + w0);
    float4 A1 = *(const float4*)(r1 + w0);
    float4 B1 = *(const float4*)(r1 + WW + w0);
    float4 A2 = *(const float4*)(r2 + w0);
    float4 B2 = *(const float4*)(r2 + WW + w0);
    const float2 t0 = *(const float2*)(r0 + hw2);
    const float2 t1 = *(const float2*)(r0 + WW + hw2);
    const float2 t2 = *(const float2*)(r1 + hw2);
    const float2 t3 = *(const float2*)(r1 + WW + hw2);
    float a4 = t0.x, a5 = t0.y, b4 = t1.x, b5 = t1.y;
    float c4 = t2.x, c5 = t2.y, d4 = t3.x, d5 = t3.y;
    float e4 = r2[hw1];
    float f4 = r2[WW + hw1];

    float u0[4] = {A0.x - B0.x, A0.y - B0.y, A0.z - B0.z, A0.w - B0.w};
    float u1[4] = {A1.x - B1.x, A1.y - B1.y, A1.z - B1.z, A1.w - B1.w};
    float u2[4] = {A2.x - B2.x, A2.y - B2.y, A2.z - B2.z, A2.w - B2.w};

    float acc0 = 0.0f, acc1 = 0.0f, acc2 = 0.0f, acc3 = 0.0f;

    #define ST(J, JC2, W1, W2) \
        step(r0, r1, r2, r3, J, JC2, w0, hw2, hw1, lastw, W1, W2, wzz0, wzz1, \
             A0, B0, A1, B1, A2, B2, a4, a5, b4, b5, c4, c5, d4, d5, e4, f4, \
             u0, u1, u2, acc0, acc1, acc2, acc3)

    if (blockIdx.x != HH / HS - 1) {
        // interior h-strip: rows h0..h0+7, all h+2 <= 505 valid
        ST(0, 2, 1.0f, 1.0f); ST(1, 3, 1.0f, 1.0f);
        ST(2, 4, 1.0f, 1.0f); ST(3, 5, 1.0f, 1.0f);
        ST(4, 6, 1.0f, 1.0f); ST(5, 7, 1.0f, 1.0f);
        ST(6, 8, 1.0f, 1.0f); ST(7, 9, 1.0f, 1.0f);
    } else {
        // last strip (h0 = 504): clamp row h+2 at 511, zero invalid h-terms
        ST(0, 2, 1.0f, 1.0f); ST(1, 3, 1.0f, 1.0f);
        ST(2, 4, 1.0f, 1.0f); ST(3, 5, 1.0f, 1.0f);
        ST(4, 6, 1.0f, 1.0f); ST(5, 7, 1.0f, 1.0f);
        ST(6, 7, 1.0f, 0.0f);   // h=510: h+2 invalid
        ST(7, 7, 0.0f, 0.0f);   // h=511: h+1, h+2 invalid
    }
    #undef ST

    float acc = (acc0 + acc1) + (acc2 + acc3);

    // ---- reduction: warp -> block -> device scratch -> last block writes ----
    acc += __shfl_xor_sync(0xffffffffu, acc, 16);
    acc += __shfl_xor_sync(0xffffffffu, acc, 8);
    acc += __shfl_xor_sync(0xffffffffu, acc, 4);
    acc += __shfl_xor_sync(0xffffffffu, acc, 2);
    acc += __shfl_xor_sync(0xffffffffu, acc, 1);

    __shared__ float warpsum[4];
    if (lane == 0) warpsum[tid >> 5] = acc;
    __syncthreads();
    if (tid == 0) {
        const float bsum = warpsum[0] + warpsum[1] + warpsum[2] + warpsum[3];
        atomicAdd(&g_acc, bsum);
        __threadfence();
        const unsigned old = atomicInc(&g_cnt, NBLK - 1);  // wraps to 0 on last
        if (old == NBLK - 1) {
            const float total = atomicExch(&g_acc, 0.0f);  // read + reset for replay
            out[0] = total * (1.0f / ((float)HH * (float)WW));
        }
    }
}

extern "C" void kernel_launch(void* const* d_in, const int* in_sizes, int n_in,
                              void* d_out, int out_size) {
    const float* img = (const float*)d_in[0];
    float* out = (float*)d_out;
    (void)in_sizes; (void)n_in; (void)out_size;

    dim3 grid(HH / HS, DD / 2, NN);   // 64 x 32 x 2 = 4096 blocks
    hess_kernel<<<grid, 128>>>(img, out);
}